// round 9
// baseline (speedup 1.0000x reference)
#include <cuda_runtime.h>
#include <cuda_bf16.h>
#include <cstdint>

#define NROWS   65536       // 4*2048*8 query rows
#define D       256
#define SUB     128
#define NC      1024
#define KOUT    16
#define TM      32          // rows per gemm block
#define THREADS 1024

#define TILE_F  8192                         // 8 k x 1024 cols (floats)
#define OFF_CT  0                            // 2 x 32 KB
#define OFF_QN  (2 * TILE_F * 4)             // 65536
#define OFF_SC  (OFF_QN + TM * SUB * 4)      // 81920
#define SMEM_BYTES (OFF_SC + TM * NC * 4)    // 212992

// pre-swizzled centroids: [m][16 tiles][2048 16B-units]
__device__ float g_ct[2 * 16 * TILE_F];
__device__ float g_tv[2][NROWS * KOUT];
__device__ int   g_ti[2][NROWS * KOUT];

__device__ __forceinline__ void cp_async16(void* dst, const void* src) {
    uint32_t d32 = (uint32_t)__cvta_generic_to_shared(dst);
    asm volatile("cp.async.cg.shared.global [%0], [%1], 16;" :: "r"(d32), "l"(src));
}

// order-preserving float<->uint bijection
__device__ __forceinline__ uint32_t fmono(float f) {
    uint32_t u = __float_as_uint(f);
    return u ^ ((uint32_t)((int32_t)u >> 31) | 0x80000000u);
}
__device__ __forceinline__ float fmono_inv(uint32_t m) {
    uint32_t u = (m & 0x80000000u) ? (m ^ 0x80000000u) : ~m;
    return __uint_as_float(u);
}
__device__ __forceinline__ uint32_t um(uint32_t a, uint32_t b) { return a > b ? a : b; }

// ---------------------------------------------------------------------------
// Kernel 0: rearrange C[1024][128] into swizzled k-tiled layout.
// ---------------------------------------------------------------------------
__global__ __launch_bounds__(256)
void pkr_prep(const float* __restrict__ ck, const float* __restrict__ cpk)
{
    const int m = blockIdx.x >> 4;
    const int t = blockIdx.x & 15;
    const float* C = m ? cpk : ck;
    float* dst = g_ct + m * 16 * TILE_F + t * TILE_F;
    for (int i = threadIdx.x; i < 2048; i += 256) {
        int c = i >> 1, s = i & 1;
        int u = i ^ ((i >> 4) & 7);
        *(float4*)&dst[u * 4] = *(const float4*)&C[c * SUB + t * 8 + s * 4];
    }
}

// ---------------------------------------------------------------------------
// Kernel 1: LN + per-subspace GEMM (32 x 1024 x 128) + per-row top-16
// grid = 4096: blockIdx>>1 = row tile, blockIdx&1 = subspace. 1024 threads.
// ---------------------------------------------------------------------------
__global__ __launch_bounds__(THREADS, 1)
void pkr_gemm(const float* __restrict__ q,
              const float* __restrict__ gamma,
              const float* __restrict__ beta)
{
    extern __shared__ char smraw[];
    float* ct = (float*)(smraw + OFF_CT);
    float* qn = (float*)(smraw + OFF_QN);   // [row][128] local k
    float* sc = (float*)(smraw + OFF_SC);

    const int tx   = threadIdx.x;
    const int warp = tx >> 5;
    const int lane = tx & 31;
    const int m    = blockIdx.x & 1;
    const long base = (long)(blockIdx.x >> 1) * TM;

    const float* gsrc = g_ct + m * 16 * TILE_F;

    auto prefetch = [&](int t, int buf) {
        const float* src = gsrc + t * TILE_F;
        float* dst = ct + buf * TILE_F;
        #pragma unroll
        for (int i = 0; i < 2; i++) {
            int e = (tx + THREADS * i) * 4;
            cp_async16(dst + e, src + e);
        }
        asm volatile("cp.async.commit_group;");
    };

    prefetch(0, 0);
    prefetch(1, 1);

    // ---- LayerNorm: warp w handles row w (32 rows); keep our 128-half
    {
        const int row = warp;
        const float* qrow = q + (base + row) * D;
        float v[8];
        float s = 0.f, s2 = 0.f;
        #pragma unroll
        for (int i = 0; i < 8; i++) {
            v[i] = qrow[lane + 32 * i];
            s  += v[i];
            s2 += v[i] * v[i];
        }
        #pragma unroll
        for (int o = 16; o; o >>= 1) {
            s  += __shfl_xor_sync(0xffffffffu, s,  o);
            s2 += __shfl_xor_sync(0xffffffffu, s2, o);
        }
        float mu  = s * (1.f / D);
        float var = s2 * (1.f / D) - mu * mu;
        float inv = rsqrtf(var + 1e-5f);
        #pragma unroll
        for (int i = 0; i < 4; i++) {
            int ig = i + 4 * m;             // d = lane + 32*ig
            int d  = lane + 32 * ig;
            qn[row * SUB + (d - m * SUB)] =
                (v[ig] - mu) * inv * gamma[d] + beta[d];
        }
    }

    // ---- GEMM: thread tile 4 rows x 8 cols over full 1024 cols
    const int c_g = tx & 127;               // cols 8*c_g .. 8*c_g+7
    const int r_g = tx >> 7;                // rows 4*r_g .. 4*r_g+3 (8 groups)
    const int sw  = c_g & 7;

    float acc[4][8];
    #pragma unroll
    for (int r = 0; r < 4; r++)
        #pragma unroll
        for (int j = 0; j < 8; j++) acc[r][j] = 0.f;

    for (int t = 0; t < 16; t++) {
        if (t < 14) {
            asm volatile("cp.async.wait_group 1;");
        } else {
            asm volatile("cp.async.wait_group 0;");
        }
        __syncthreads();

        const float4* ctb = (const float4*)(ct + (t & 1) * TILE_F);
        const float4* qn4 = (const float4*)qn;

        #pragma unroll
        for (int s = 0; s < 2; s++) {
            const int k4 = t * 2 + s;
            float4 qv[4];
            #pragma unroll
            for (int r = 0; r < 4; r++)
                qv[r] = qn4[(4 * r_g + r) * 32 + k4];
            #pragma unroll
            for (int j = 0; j < 8; j++) {
                const int c = 8 * c_g + j;
                float4 cc = ctb[(c * 2 + s) ^ sw];
                #pragma unroll
                for (int r = 0; r < 4; r++) {
                    acc[r][j] = fmaf(qv[r].x, cc.x, acc[r][j]);
                    acc[r][j] = fmaf(qv[r].y, cc.y, acc[r][j]);
                    acc[r][j] = fmaf(qv[r].z, cc.z, acc[r][j]);
                    acc[r][j] = fmaf(qv[r].w, cc.w, acc[r][j]);
                }
            }
        }
        __syncthreads();

        if (t < 14) prefetch(t + 2, t & 1);
    }

    // ---- write scores
    #pragma unroll
    for (int r = 0; r < 4; r++) {
        const int row = 4 * r_g + r;
        *(float4*)&sc[row * NC + 8 * c_g] =
            make_float4(acc[r][0], acc[r][1], acc[r][2], acc[r][3]);
        *(float4*)&sc[row * NC + 8 * c_g + 4] =
            make_float4(acc[r][4], acc[r][5], acc[r][6], acc[r][7]);
    }
    __syncthreads();

    // ---- per-row top-16 of 1024: tournament with exact min-index ties
    {
        const int row = warp;
        uint32_t mv[32];
        #pragma unroll
        for (int i = 0; i < 32; i++)
            mv[i] = fmono(sc[row * NC + lane + 32 * i]);

        uint32_t g0, g1, g2, g3;
        #define GMAX8(B) um(um(um(mv[B],mv[B+1]),um(mv[B+2],mv[B+3])), \
                            um(um(mv[B+4],mv[B+5]),um(mv[B+6],mv[B+7])))
        g0 = GMAX8(0); g1 = GMAX8(8); g2 = GMAX8(16); g3 = GMAX8(24);

        long gb = (base + row) * KOUT;
        for (int r16 = 0; r16 < 16; r16++) {
            uint32_t lm = um(um(g0, g1), um(g2, g3));
            uint32_t wm = __reduce_max_sync(0xffffffffu, lm);
            uint32_t cand = 0xffffffffu;
            int e = 0;
            if (lm == wm) {
                if (g0 == wm) {
                    #pragma unroll
                    for (int j = 7; j >= 0; j--) if (mv[j] == wm) e = j;
                } else if (g1 == wm) {
                    e = 8;
                    #pragma unroll
                    for (int j = 15; j >= 8; j--) if (mv[j] == wm) e = j;
                } else if (g2 == wm) {
                    e = 16;
                    #pragma unroll
                    for (int j = 23; j >= 16; j--) if (mv[j] == wm) e = j;
                } else {
                    e = 24;
                    #pragma unroll
                    for (int j = 31; j >= 24; j--) if (mv[j] == wm) e = j;
                }
                cand = (uint32_t)(lane + 32 * e);
            }
            uint32_t gidx = __reduce_min_sync(0xffffffffu, cand);
            if (cand == gidx) {
                if (e < 8) {
                    #pragma unroll
                    for (int j = 0; j < 8; j++) mv[j] = (j == e) ? 0u : mv[j];
                    g0 = GMAX8(0);
                } else if (e < 16) {
                    #pragma unroll
                    for (int j = 8; j < 16; j++) mv[j] = (j == e) ? 0u : mv[j];
                    g1 = GMAX8(8);
                } else if (e < 24) {
                    #pragma unroll
                    for (int j = 16; j < 24; j++) mv[j] = (j == e) ? 0u : mv[j];
                    g2 = GMAX8(16);
                } else {
                    #pragma unroll
                    for (int j = 24; j < 32; j++) mv[j] = (j == e) ? 0u : mv[j];
                    g3 = GMAX8(24);
                }
            }
            if (lane == 0) {
                g_tv[m][gb + r16] = fmono_inv(wm);
                g_ti[m][gb + r16] = (int)gidx;
            }
        }
        #undef GMAX8
    }
}

// ---------------------------------------------------------------------------
// Kernel 2: joint 16x16 top-16 + output. 8 rows/block, 1 row per warp.
// ---------------------------------------------------------------------------
__global__ __launch_bounds__(256, 1)
void pkr_joint(float* __restrict__ out)
{
    __shared__ float s1v[8 * KOUT], s2v[8 * KOUT];
    __shared__ int   s1i[8 * KOUT], s2i[8 * KOUT];

    const int tx   = threadIdx.x;
    const int warp = tx >> 5;
    const int lane = tx & 31;
    const long base = (long)blockIdx.x * 8;

    if (tx < 128) {
        long g = base * KOUT + tx;
        s1v[tx] = g_tv[0][g];
        s1i[tx] = g_ti[0][g];
    } else {
        int t2 = tx - 128;
        long g = base * KOUT + t2;
        s2v[t2] = g_tv[1][g];
        s2i[t2] = g_ti[1][g];
    }
    __syncthreads();

    const int row = warp;
    uint32_t mv[8];
    #pragma unroll
    for (int u = 0; u < 8; u++) {
        int f = lane + 32 * u;
        mv[u] = fmono(s1v[row * KOUT + (f >> 4)] + s2v[row * KOUT + (f & 15)]);
    }

    long R = base + row;
    for (int r16 = 0; r16 < 16; r16++) {
        uint32_t lm = um(um(um(mv[0], mv[1]), um(mv[2], mv[3])),
                         um(um(mv[4], mv[5]), um(mv[6], mv[7])));
        uint32_t wm = __reduce_max_sync(0xffffffffu, lm);
        uint32_t cand = 0xffffffffu;
        int e = 0;
        if (lm == wm) {
            #pragma unroll
            for (int j = 7; j >= 0; j--) if (mv[j] == wm) e = j;
            cand = (uint32_t)(lane + 32 * e);
        }
        uint32_t f = __reduce_min_sync(0xffffffffu, cand);
        if (cand == f) {
            #pragma unroll
            for (int j = 0; j < 8; j++) mv[j] = (j == e) ? 0u : mv[j];
        }
        if (lane == 0) {
            int i16 = (int)(f >> 4) & 15;   // f = i16*16 + j16 (flat joint idx)
            int j16 = (int)(f & 15);
            int gidx = s1i[row * KOUT + i16] * NC + s2i[row * KOUT + j16];
            out[R * KOUT + r16]                      = (float)gidx;
            out[(long)NROWS * KOUT + R * KOUT + r16] = fmono_inv(wm);
        }
    }
}

extern "C" void kernel_launch(void* const* d_in, const int* in_sizes, int n_in,
                              void* d_out, int out_size)
{
    const float* q     = (const float*)d_in[0];
    const float* ck    = (const float*)d_in[1];
    const float* cpk   = (const float*)d_in[2];
    const float* gamma = (const float*)d_in[3];
    const float* beta  = (const float*)d_in[4];
    float* out = (float*)d_out;

    cudaFuncSetAttribute(pkr_gemm,
                         cudaFuncAttributeMaxDynamicSharedMemorySize, SMEM_BYTES);

    pkr_prep<<<32, 256>>>(ck, cpk);
    pkr_gemm<<<(NROWS / TM) * 2, THREADS, SMEM_BYTES>>>(q, gamma, beta);
    pkr_joint<<<NROWS / 8, 256>>>(out);
}

// round 13
// speedup vs baseline: 1.2410x; 1.2410x over previous
#include <cuda_runtime.h>
#include <cuda_bf16.h>
#include <cstdint>

#define NROWS 65536        // 4*2048*8 query rows
#define D     256
#define SUB   128
#define NC    1024
#define KOUT  16
#define MR    64           // query rows per mm block
#define MMT   256          // threads (8 warps)
#define NCAND 32           // HMMA candidates per list

#define A_SPLIT  16384                  // 64 rows x 128k bf16 (swizzled)
#define OFF_A    0                      // 2 splits = 32768
#define B_CHUNK  32768                  // 128 cols x 128k bf16 (swizzled)
#define OFF_B    (2 * A_SPLIT)          // 32768
#define SMEM_MM  (OFF_B + 2 * B_CHUNK)  // 98304

// C splits (h,m), swizzled smem image: [(m*8+ph)*2 + split] blocks of 32 KB
__device__ __align__(16) uint8_t g_cb[32 * B_CHUNK];     // 1 MB
__device__ float g_sc[(size_t)2 * NROWS * NC];           // 512 MB scores
__device__ float g_tv[2][NROWS * KOUT];
__device__ int   g_ti[2][NROWS * KOUT];

__device__ __forceinline__ uint32_t smem_u32(const void* p) {
    return (uint32_t)__cvta_generic_to_shared(p);
}
__device__ __forceinline__ void cp_async16(void* dst, const void* src) {
    asm volatile("cp.async.cg.shared.global [%0], [%1], 16;"
                 :: "r"(smem_u32(dst)), "l"(src));
}
__device__ __forceinline__ uint32_t fmono(float f) {
    uint32_t u = __float_as_uint(f);
    return u ^ ((uint32_t)((int32_t)u >> 31) | 0x80000000u);
}
__device__ __forceinline__ float fmono_inv(uint32_t m) {
    uint32_t u = (m & 0x80000000u) ? (m ^ 0x80000000u) : ~m;
    return __uint_as_float(u);
}
__device__ __forceinline__ uint32_t um(uint32_t a, uint32_t b) { return a > b ? a : b; }

// 2-way bf16 split (h + m captures 16 mantissa bits)
__device__ __forceinline__ void bsplit2(float c, unsigned short& h, unsigned short& mm) {
    __nv_bfloat16 bh = __float2bfloat16(c);
    float r1 = c - __bfloat162float(bh);
    __nv_bfloat16 bm = __float2bfloat16(r1);
    h  = __bfloat16_as_ushort(bh);
    mm = __bfloat16_as_ushort(bm);
}

// ---------------------------------------------------------------------------
// Kernel 0: build h,m bf16 splits of C in the swizzled smem image.
// Element (nloc, k): byte = nloc*256 + (((k>>3) ^ (nloc&7))<<4) + (k&7)*2
// ---------------------------------------------------------------------------
__global__ __launch_bounds__(256)
void pkr_prepb(const float* __restrict__ ck, const float* __restrict__ cpk)
{
    const int m  = blockIdx.x >> 3;
    const int ph = blockIdx.x & 7;
    const float* C = m ? cpk : ck;
    uint8_t* dst0 = g_cb + (size_t)((m * 8 + ph) * 2) * B_CHUNK;

    for (int i = threadIdx.x; i < 128 * 128; i += 256) {
        int nloc = i >> 7, k = i & 127;
        unsigned short h, mm;
        bsplit2(C[(ph * 128 + nloc) * SUB + k], h, mm);
        uint32_t byte = (uint32_t)(nloc * 256 + (((k >> 3) ^ (nloc & 7)) << 4)
                                   + (k & 7) * 2);
        *(unsigned short*)(dst0 + 0 * B_CHUNK + byte) = h;
        *(unsigned short*)(dst0 + 1 * B_CHUNK + byte) = mm;
    }
}

// ---------------------------------------------------------------------------
// Kernel 1: LN + 3-pair bf16 HMMA GEMM (hh+hm+mh). grid 2048. 8 warps.
// ---------------------------------------------------------------------------
__global__ __launch_bounds__(MMT, 1)
void pkr_mm(const float* __restrict__ q,
            const float* __restrict__ gamma,
            const float* __restrict__ beta)
{
    extern __shared__ char sm[];
    const uint32_t smb = smem_u32(sm);

    const int tx   = threadIdx.x;
    const int warp = tx >> 5;
    const int lane = tx & 31;
    const int m    = blockIdx.x & 1;
    const long base = (long)(blockIdx.x >> 1) * MR;

    static const int splitA[3] = {0, 0, 1};
    static const int splitB[3] = {0, 1, 0};

    auto prefetch = [&](int g, int buf) {
        const int ph = g / 3, kc = g % 3;
        const uint8_t* src = g_cb + (size_t)((m * 8 + ph) * 2 + splitB[kc]) * B_CHUNK;
        char* dst = sm + OFF_B + buf * B_CHUNK;
        #pragma unroll
        for (int i = 0; i < 8; i++) {
            int e = (tx + MMT * i) * 16;
            cp_async16(dst + e, src + e);
        }
        asm volatile("cp.async.commit_group;");
    };
    prefetch(0, 0);
    prefetch(1, 1);

    // ---- LayerNorm + q h,m splits -> A smem (R8-identical LN order)
    for (int rr = 0; rr < 8; rr++) {
        const int row = rr * 8 + warp;
        const float* qrow = q + (base + row) * D;
        float v[8];
        float s = 0.f, s2 = 0.f;
        #pragma unroll
        for (int i = 0; i < 8; i++) {
            v[i] = qrow[lane + 32 * i];
            s  += v[i];
            s2 += v[i] * v[i];
        }
        #pragma unroll
        for (int o = 16; o; o >>= 1) {
            s  += __shfl_xor_sync(0xffffffffu, s,  o);
            s2 += __shfl_xor_sync(0xffffffffu, s2, o);
        }
        float mu  = s * (1.f / D);
        float var = s2 * (1.f / D) - mu * mu;
        float inv = rsqrtf(var + 1e-5f);
        #pragma unroll
        for (int i = 0; i < 4; i++) {
            int ig = i + 4 * m;             // d = lane + 32*ig
            int d  = lane + 32 * ig;
            int kl = d - m * SUB;
            float val = (v[ig] - mu) * inv * gamma[d] + beta[d];
            unsigned short h, mm;
            bsplit2(val, h, mm);
            uint32_t byte = (uint32_t)(row * 256 + (((kl >> 3) ^ (row & 7)) << 4)
                                       + (kl & 7) * 2);
            *(unsigned short*)(sm + OFF_A + 0 * A_SPLIT + byte) = h;
            *(unsigned short*)(sm + OFF_A + 1 * A_SPLIT + byte) = mm;
        }
    }
    __syncthreads();

    // ---- main loop: 8 N-phases x 3 pairs; warp tile 32 rows x 32 cols
    const int wr = warp >> 2;
    const int wc = warp & 3;
    float dacc[2][4][4];
    #pragma unroll
    for (int a = 0; a < 2; a++)
        #pragma unroll
        for (int b = 0; b < 4; b++)
            #pragma unroll
            for (int c = 0; c < 4; c++) dacc[a][b][c] = 0.f;

    for (int g = 0; g < 24; g++) {
        const int kc = g % 3;
        if (g < 23) asm volatile("cp.async.wait_group 1;");
        else        asm volatile("cp.async.wait_group 0;");
        __syncthreads();

        const uint32_t abase = smb + OFF_A + splitA[kc] * A_SPLIT;
        const uint32_t bbase = smb + OFF_B + (g & 1) * B_CHUNK;

        #pragma unroll
        for (int ks = 0; ks < 8; ks++) {
            uint32_t af[2][4];
            #pragma unroll
            for (int mt = 0; mt < 2; mt++) {
                int row = wr * 32 + mt * 16 + (lane & 15);
                int k8  = (ks * 2 + (lane >> 4)) ^ (row & 7);
                uint32_t addr = abase + (uint32_t)(row * 256 + k8 * 16);
                asm volatile("ldmatrix.sync.aligned.m8n8.x4.shared.b16 "
                             "{%0,%1,%2,%3}, [%4];"
                             : "=r"(af[mt][0]), "=r"(af[mt][1]),
                               "=r"(af[mt][2]), "=r"(af[mt][3]) : "r"(addr));
            }
            uint32_t bf[4][2];
            const int l2 = lane & 15;
            #pragma unroll
            for (int nt = 0; nt < 4; nt++) {
                int col = wc * 32 + nt * 8 + (l2 & 7);
                int k8  = (ks * 2 + (l2 >> 3)) ^ (col & 7);
                uint32_t addr = bbase + (uint32_t)(col * 256 + k8 * 16);
                asm volatile("ldmatrix.sync.aligned.m8n8.x2.shared.b16 "
                             "{%0,%1}, [%2];"
                             : "=r"(bf[nt][0]), "=r"(bf[nt][1]) : "r"(addr));
            }
            #pragma unroll
            for (int mt = 0; mt < 2; mt++)
                #pragma unroll
                for (int nt = 0; nt < 4; nt++)
                    asm volatile(
                        "mma.sync.aligned.m16n8k16.row.col.f32.bf16.bf16.f32 "
                        "{%0,%1,%2,%3}, {%4,%5,%6,%7}, {%8,%9}, {%0,%1,%2,%3};"
                        : "+f"(dacc[mt][nt][0]), "+f"(dacc[mt][nt][1]),
                          "+f"(dacc[mt][nt][2]), "+f"(dacc[mt][nt][3])
                        : "r"(af[mt][0]), "r"(af[mt][1]),
                          "r"(af[mt][2]), "r"(af[mt][3]),
                          "r"(bf[nt][0]), "r"(bf[nt][1]));
        }
        __syncthreads();
        if (g + 2 < 24) prefetch(g + 2, g & 1);

        if (kc == 2) {
            const int ph = g / 3;
            #pragma unroll
            for (int mt = 0; mt < 2; mt++) {
                #pragma unroll
                for (int nt = 0; nt < 4; nt++) {
                    long row0 = base + wr * 32 + mt * 16 + (lane >> 2);
                    int  col  = ph * 128 + wc * 32 + nt * 8 + (lane & 3) * 2;
                    float* p0 = g_sc + ((size_t)m * NROWS + row0) * NC + col;
                    float* p1 = p0 + 8 * NC;
                    *(float2*)p0 = make_float2(dacc[mt][nt][0], dacc[mt][nt][1]);
                    *(float2*)p1 = make_float2(dacc[mt][nt][2], dacc[mt][nt][3]);
                    #pragma unroll
                    for (int c = 0; c < 4; c++) dacc[mt][nt][c] = 0.f;
                }
            }
        }
    }
}

// ---------------------------------------------------------------------------
// Kernel 2: top-32 candidates by HMMA score, exact fp32 rescore (sequential-k
// chain, R8 order), exact top-16. 1 task per warp, 8 warps/block.
// ---------------------------------------------------------------------------
__global__ __launch_bounds__(256, 1)
void pkr_sel(const float* __restrict__ q,
             const float* __restrict__ ck,
             const float* __restrict__ cpk,
             const float* __restrict__ gamma,
             const float* __restrict__ beta)
{
    __shared__ float qn_s[8 * SUB];

    const int tx   = threadIdx.x;
    const int warp = tx >> 5;
    const int lane = tx & 31;
    const size_t task = (size_t)blockIdx.x * 8 + warp;
    const int m   = (int)(task >> 16);
    const int row = (int)(task & 65535);

    // ---- LN recompute (bit-identical to mm/R8 order), our half -> smem
    {
        const float* qrow = q + (size_t)row * D;
        float v[8];
        float s = 0.f, s2 = 0.f;
        #pragma unroll
        for (int i = 0; i < 8; i++) {
            v[i] = qrow[lane + 32 * i];
            s  += v[i];
            s2 += v[i] * v[i];
        }
        #pragma unroll
        for (int o = 16; o; o >>= 1) {
            s  += __shfl_xor_sync(0xffffffffu, s,  o);
            s2 += __shfl_xor_sync(0xffffffffu, s2, o);
        }
        float mu  = s * (1.f / D);
        float var = s2 * (1.f / D) - mu * mu;
        float inv = rsqrtf(var + 1e-5f);
        #pragma unroll
        for (int i = 0; i < 4; i++) {
            int ig = i + 4 * m;
            int d  = lane + 32 * ig;
            qn_s[warp * SUB + (d - m * SUB)] =
                (v[ig] - mu) * inv * gamma[d] + beta[d];
        }
    }
    __syncwarp();

    // ---- tournament: top-32 candidate indices from HMMA scores
    const float* src = g_sc + task * NC;
    uint32_t mv[32];
    #pragma unroll
    for (int i = 0; i < 32; i++)
        mv[i] = fmono(src[lane + 32 * i]);

    uint32_t g0, g1, g2, g3;
    #define GMAX8(B) um(um(um(mv[B],mv[B+1]),um(mv[B+2],mv[B+3])), \
                        um(um(mv[B+4],mv[B+5]),um(mv[B+6],mv[B+7])))
    g0 = GMAX8(0); g1 = GMAX8(8); g2 = GMAX8(16); g3 = GMAX8(24);

    int myCand = 0;
    for (int r = 0; r < NCAND; r++) {
        uint32_t lm = um(um(g0, g1), um(g2, g3));
        uint32_t wm = __reduce_max_sync(0xffffffffu, lm);
        uint32_t cand = 0xffffffffu;
        int e = 0;
        if (lm == wm) {
            if (g0 == wm) {
                #pragma unroll
                for (int j = 7; j >= 0; j--) if (mv[j] == wm) e = j;
            } else if (g1 == wm) {
                e = 8;
                #pragma unroll
                for (int j = 15; j >= 8; j--) if (mv[j] == wm) e = j;
            } else if (g2 == wm) {
                e = 16;
                #pragma unroll
                for (int j = 23; j >= 16; j--) if (mv[j] == wm) e = j;
            } else {
                e = 24;
                #pragma unroll
                for (int j = 31; j >= 24; j--) if (mv[j] == wm) e = j;
            }
            cand = (uint32_t)(lane + 32 * e);
        }
        uint32_t gidx = __reduce_min_sync(0xffffffffu, cand);
        if (cand == gidx) {
            if (e < 8) {
                #pragma unroll
                for (int j = 0; j < 8; j++) mv[j] = (j == e) ? 0u : mv[j];
                g0 = GMAX8(0);
            } else if (e < 16) {
                #pragma unroll
                for (int j = 8; j < 16; j++) mv[j] = (j == e) ? 0u : mv[j];
                g1 = GMAX8(8);
            } else if (e < 24) {
                #pragma unroll
                for (int j = 16; j < 24; j++) mv[j] = (j == e) ? 0u : mv[j];
                g2 = GMAX8(16);
            } else {
                #pragma unroll
                for (int j = 24; j < 32; j++) mv[j] = (j == e) ? 0u : mv[j];
                g3 = GMAX8(24);
            }
        }
        if (lane == r) myCand = (int)gidx;
    }
    #undef GMAX8

    // ---- exact fp32 rescore: sequential-k chain (R8 order)
    const float* Cm = m ? cpk : ck;
    float acc = 0.f;
    {
        const float4* c4 = (const float4*)(Cm + (size_t)myCand * SUB);
        const float4* q4 = (const float4*)(qn_s + warp * SUB);
        #pragma unroll 8
        for (int k4 = 0; k4 < 32; k4++) {
            float4 cc = c4[k4];
            float4 qq = q4[k4];
            acc = fmaf(qq.x, cc.x, acc);
            acc = fmaf(qq.y, cc.y, acc);
            acc = fmaf(qq.z, cc.z, acc);
            acc = fmaf(qq.w, cc.w, acc);
        }
    }

    // ---- exact top-16 of the 32 candidates (value desc, index asc)
    uint32_t myMono = fmono(acc);
    const long gb = (long)row * KOUT;
    for (int r = 0; r < KOUT; r++) {
        uint32_t wm = __reduce_max_sync(0xffffffffu, myMono);
        uint32_t cand = (myMono == wm) ? (uint32_t)myCand : 0xffffffffu;
        uint32_t gi = __reduce_min_sync(0xffffffffu, cand);
        if (lane == 0) {
            g_tv[m][gb + r] = fmono_inv(wm);
            g_ti[m][gb + r] = (int)gi;
        }
        if ((uint32_t)myCand == gi) myMono = 0u;
    }
}

// ---------------------------------------------------------------------------
// Kernel 3: joint 16x16 top-16 + output. 8 rows/block, 1 row per warp.
// ---------------------------------------------------------------------------
__global__ __launch_bounds__(256, 1)
void pkr_joint(float* __restrict__ out)
{
    __shared__ float s1v[8 * KOUT], s2v[8 * KOUT];
    __shared__ int   s1i[8 * KOUT], s2i[8 * KOUT];

    const int tx   = threadIdx.x;
    const int warp = tx >> 5;
    const int lane = tx & 31;
    const long base = (long)blockIdx.x * 8;

    if (tx < 128) {
        long g = base * KOUT + tx;
        s1v[tx] = g_tv[0][g];
        s1i[tx] = g_ti[0][g];
    } else {
        int t2 = tx - 128;
        long g = base * KOUT + t2;
        s2v[t2] = g_tv[1][g];
        s2i[t2] = g_ti[1][g];
    }
    __syncthreads();

    const int row = warp;
    uint32_t mv[8];
    #pragma unroll
    for (int u = 0; u < 8; u++) {
        int f = lane + 32 * u;
        mv[u] = fmono(s1v[row * KOUT + (f >> 4)] + s2v[row * KOUT + (f & 15)]);
    }

    long R = base + row;
    for (int r16 = 0; r16 < 16; r16++) {
        uint32_t lm = um(um(um(mv[0], mv[1]), um(mv[2], mv[3])),
                         um(um(mv[4], mv[5]), um(mv[6], mv[7])));
        uint32_t wm = __reduce_max_sync(0xffffffffu, lm);
        uint32_t cand = 0xffffffffu;
        int e = 0;
        if (lm == wm) {
            #pragma unroll
            for (int j = 7; j >= 0; j--) if (mv[j] == wm) e = j;
            cand = (uint32_t)(lane + 32 * e);
        }
        uint32_t f = __reduce_min_sync(0xffffffffu, cand);
        if (cand == f) {
            #pragma unroll
            for (int j = 0; j < 8; j++) mv[j] = (j == e) ? 0u : mv[j];
        }
        if (lane == 0) {
            int i16 = (int)(f >> 4) & 15;
            int j16 = (int)(f & 15);
            int gidx = s1i[row * KOUT + i16] * NC + s2i[row * KOUT + j16];
            out[R * KOUT + r16]                      = (float)gidx;
            out[(long)NROWS * KOUT + R * KOUT + r16] = fmono_inv(wm);
        }
    }
}

extern "C" void kernel_launch(void* const* d_in, const int* in_sizes, int n_in,
                              void* d_out, int out_size)
{
    const float* q     = (const float*)d_in[0];
    const float* ck    = (const float*)d_in[1];
    const float* cpk   = (const float*)d_in[2];
    const float* gamma = (const float*)d_in[3];
    const float* beta  = (const float*)d_in[4];
    float* out = (float*)d_out;

    cudaFuncSetAttribute(pkr_mm,
                         cudaFuncAttributeMaxDynamicSharedMemorySize, SMEM_MM);

    pkr_prepb<<<16, 256>>>(ck, cpk);
    pkr_mm<<<(NROWS / MR) * 2, MMT, SMEM_MM>>>(q, gamma, beta);
    pkr_sel<<<(2 * NROWS) / 8, 256>>>(q, ck, cpk, gamma, beta);
    pkr_joint<<<NROWS / 8, 256>>>(out);
}